// round 4
// baseline (speedup 1.0000x reference)
#include <cuda_runtime.h>
#include <cstdint>

#define N_CELL 200000
#define N_WELL 2000
#define E_CC   1200000
#define E_CW   200000
#define CF     16
#define WF     8
#define H      128
#define OUT    75
#define WPB    8
#define R      16

// ---------------- device scratch ----------------
__device__ __align__(16) float g_aggx[(size_t)N_CELL * CF];
__device__ int      g_cnt[N_CELL];
__device__ unsigned g_bm[(N_CELL + 31) / 32];
__device__ __align__(16) float g_Ur[(size_t)R * N_WELL * CF];
__device__ __align__(16) float g_Vr[(size_t)R * N_WELL * CF];
__device__ __align__(16) float g_meta[(size_t)R * N_WELL * 4];

// fused-weight pipeline: T1 (43x128), T2 (34x128), F (43x128)
// F rows: [0,16) M1 (Un), [16,32) M2 (Vn), 32 v1 (beta_n), 33 v2 (mask),
//         [34,42) M3 (wx), 42 v3 (const)
__device__ float g_T1[43 * H];
__device__ float g_T2[34 * H];
__device__ float g_F[43 * H];

__device__ __forceinline__ void red4(float* p, float a, float b, float c, float d) {
    asm volatile("red.global.add.v4.f32 [%0], {%1,%2,%3,%4};"
                 :: "l"(p), "f"(a), "f"(b), "f"(c), "f"(d) : "memory");
}

// ---------------- K1: zero state ----------------
__global__ void k_init() {
    int i = blockIdx.x * blockDim.x + threadIdx.x;
    if (i < N_CELL * CF) g_aggx[i] = 0.f;
    if (i < N_CELL)      g_cnt[i]  = 0;
    if (i < (N_CELL + 31) / 32) g_bm[i] = 0u;
    if (i < R * N_WELL * CF) { g_Ur[i] = 0.f; g_Vr[i] = 0.f; }
    if (i < R * N_WELL * 4)  g_meta[i] = 0.f;
}

// ---------------- K2: mark active cells ----------------
__global__ void k_mark(const int* __restrict__ ews) {
    int e = blockIdx.x * blockDim.x + threadIdx.x;
    if (e >= E_CW) return;
    int s = __ldg(&ews[e]);
    atomicOr(&g_bm[s >> 5], 1u << (s & 31));
}

// ---------------- generic stage body: one output row per block, 256 thr ----
__device__ __forceinline__ void stage_row(const float* __restrict__ L,
                                          const float* __restrict__ M,
                                          float* __restrict__ dst,
                                          const float* __restrict__ addv,
                                          float* sL, float* sP)
{
    int tid  = threadIdx.x;
    int h    = tid & (H - 1);
    int half = tid >> 7;              // 0 or 1
    if (half == 0) sL[h] = __ldg(&L[h]);
    __syncthreads();
    float acc = 0.f;
    int k0 = half * 64;
#pragma unroll 16
    for (int k = 0; k < 64; k++)
        acc += sL[k0 + k] * __ldg(&M[(k0 + k) * H + h]);
    sP[tid] = acc;
    __syncthreads();
    if (half == 0) {
        float v = sP[h] + sP[h + 128];
        if (addv) v += __ldg(&addv[h]);
        dst[h] = v;
    }
}

// ---------------- F1: first-stage products (43 rows) ----------------
__global__ void __launch_bounds__(256) k_f1(
    const float* __restrict__ W_cell, const float* __restrict__ b_cell,
    const float* __restrict__ Wl_cc, const float* __restrict__ Wr_cc,
    const float* __restrict__ bl_cc,
    const float* __restrict__ W_well, const float* __restrict__ b_well,
    const float* __restrict__ Wr_cw, const float* __restrict__ bl_cw)
{
    __shared__ float sL[H];
    __shared__ float sP[256];
    int r = blockIdx.x;
    const float* L; const float* M; const float* A = nullptr;
    if (r < 16)      { L = W_cell + r * H;        M = Wl_cc; }
    else if (r < 32) { L = W_cell + (r - 16) * H; M = Wr_cc; }
    else if (r == 32){ L = b_cell;                M = Wl_cc; }
    else if (r == 33){ L = b_cell;                M = Wr_cc; A = bl_cc; }
    else if (r < 42) { L = W_well + (r - 34) * H; M = Wr_cw; }
    else             { L = b_well;                M = Wr_cw; A = bl_cw; }
    stage_row(L, M, g_T1 + r * H, A, sL, sP);
}

// ---------------- F2: cc-chain rows x Wl_cw (34 rows) ----------------
__global__ void __launch_bounds__(256) k_f2(const float* __restrict__ Wl_cw)
{
    __shared__ float sL[H];
    __shared__ float sP[256];
    int r = blockIdx.x;
    stage_row(g_T1 + r * H, Wl_cw, g_T2 + r * H, nullptr, sL, sP);
}

// ---------------- F3: all rows x Wm1 (43 rows) ----------------
__global__ void __launch_bounds__(256) k_f3(const float* __restrict__ Wm1,
                                            const float* __restrict__ bm1)
{
    __shared__ float sL[H];
    __shared__ float sP[256];
    int r = blockIdx.x;
    const float* L = (r < 34) ? (g_T2 + r * H) : (g_T1 + r * H);
    const float* A = (r == 42) ? bm1 : nullptr;
    stage_row(L, Wm1, g_F + r * H, A, sL, sP);
}

// ---------------- K3: scan cell-cell edges ----------------
__global__ void k_cc(const int* __restrict__ ei, const float* __restrict__ x) {
    int e = blockIdx.x * blockDim.x + threadIdx.x;
    if (e >= E_CC) return;
    int d = __ldg(&ei[E_CC + e]);
    if (!((g_bm[d >> 5] >> (d & 31)) & 1u)) return;
    int s = __ldg(&ei[e]);
    const float4* xp = (const float4*)(x + (size_t)s * CF);
    float* ap = g_aggx + (size_t)d * CF;
    float4 v0 = __ldg(xp + 0), v1 = __ldg(xp + 1), v2 = __ldg(xp + 2), v3 = __ldg(xp + 3);
    red4(ap + 0,  v0.x, v0.y, v0.z, v0.w);
    red4(ap + 4,  v1.x, v1.y, v1.z, v1.w);
    red4(ap + 8,  v2.x, v2.y, v2.z, v2.w);
    red4(ap + 12, v3.x, v3.y, v3.z, v3.w);
    atomicAdd(&g_cnt[d], 1);
}

// ---------------- K4: scan cell-well edges into replicated accumulators ----
__global__ void k_cw(const int* __restrict__ ews, const int* __restrict__ ewd,
                     const float* __restrict__ x) {
    int e = blockIdx.x * blockDim.x + threadIdx.x;
    if (e >= E_CW) return;
    int rep = blockIdx.x & (R - 1);
    int s = __ldg(&ews[e]);
    int w = __ldg(&ewd[e]);
    int c = g_cnt[s];
    float inv = (c > 0) ? (1.f / (float)c) : 0.f;
    const float4* ap = (const float4*)(g_aggx + (size_t)s * CF);
    const float4* xp = (const float4*)(x + (size_t)s * CF);
    float* U = g_Ur + ((size_t)rep * N_WELL + w) * CF;
    float* V = g_Vr + ((size_t)rep * N_WELL + w) * CF;
    float4 a0 = ap[0], a1 = ap[1], a2 = ap[2], a3 = ap[3];
    red4(U + 0,  a0.x * inv, a0.y * inv, a0.z * inv, a0.w * inv);
    red4(U + 4,  a1.x * inv, a1.y * inv, a1.z * inv, a1.w * inv);
    red4(U + 8,  a2.x * inv, a2.y * inv, a2.z * inv, a2.w * inv);
    red4(U + 12, a3.x * inv, a3.y * inv, a3.z * inv, a3.w * inv);
    float4 b0 = __ldg(xp + 0), b1 = __ldg(xp + 1), b2 = __ldg(xp + 2), b3 = __ldg(xp + 3);
    red4(V + 0,  b0.x, b0.y, b0.z, b0.w);
    red4(V + 4,  b1.x, b1.y, b1.z, b1.w);
    red4(V + 8,  b2.x, b2.y, b2.z, b2.w);
    red4(V + 12, b3.x, b3.y, b3.z, b3.w);
    red4(g_meta + ((size_t)rep * N_WELL + w) * 4, (c > 0) ? 1.f : 0.f, 1.f, 0.f, 0.f);
}

// ---------------- K6: per-well head using fused table g_F ----------------
__global__ void __launch_bounds__(H) k_well(
    const float* __restrict__ well_x,
    const float* __restrict__ Wm2, const float* __restrict__ bm2,
    float* __restrict__ out)
{
    __shared__ __align__(16) float sm[H][WPB];
    __shared__ float sUn[WPB][CF], sVn[WPB][CF], sWX[WPB][WF];
    __shared__ float sb1[WPB], sb2[WPB], sinv[WPB];

    int h  = threadIdx.x;
    int w0 = blockIdx.x * WPB;

    if (h < WPB) {
        float beta = 0.f, cw = 0.f;
#pragma unroll
        for (int r = 0; r < R; r++) {
            const float* mp = g_meta + ((size_t)r * N_WELL + (w0 + h)) * 4;
            beta += mp[0];
            cw   += mp[1];
        }
        float inv = 1.f / fmaxf(cw, 1.f);
        sinv[h] = inv;
        sb1[h]  = beta * inv;
        sb2[h]  = (cw > 0.5f) ? 1.f : 0.f;
    }
    __syncthreads();
    {
        int t = h >> 4, j = h & 15;
        float su = 0.f, svv = 0.f;
#pragma unroll
        for (int r = 0; r < R; r++) {
            size_t off = ((size_t)r * N_WELL + (w0 + t)) * CF + j;
            su  += g_Ur[off];
            svv += g_Vr[off];
        }
        sUn[t][j] = su * sinv[t];
        sVn[t][j] = svv * sinv[t];
    }
    if (h < WPB * WF) {
        int t = h >> 3, j = h & 7;
        sWX[t][j] = __ldg(&well_x[(w0 + t) * WF + j]);
    }
    __syncthreads();

    float acc[WPB];
    {
        float f1 = g_F[32 * H + h], f2 = g_F[33 * H + h], f3 = g_F[42 * H + h];
#pragma unroll
        for (int t = 0; t < WPB; t++) acc[t] = f3 + sb1[t] * f1 + sb2[t] * f2;
    }
#pragma unroll
    for (int j = 0; j < CF; j++) {
        float m1 = g_F[j * H + h];
        float m2 = g_F[(16 + j) * H + h];
#pragma unroll
        for (int t = 0; t < WPB; t++) acc[t] += sUn[t][j] * m1 + sVn[t][j] * m2;
    }
#pragma unroll
    for (int j = 0; j < WF; j++) {
        float m3 = g_F[(34 + j) * H + h];
#pragma unroll
        for (int t = 0; t < WPB; t++) acc[t] += sWX[t][j] * m3;
    }
#pragma unroll
    for (int t = 0; t < WPB; t++) sm[h][t] = fmaxf(acc[t], 0.f);
    __syncthreads();

    if (h < OUT) {
        float o[WPB];
        float bv = __ldg(&bm2[h]);
#pragma unroll
        for (int t = 0; t < WPB; t++) o[t] = bv;
#pragma unroll 4
        for (int k = 0; k < H; k++) {
            float wm = __ldg(&Wm2[k * OUT + h]);
            float4 p0 = *(const float4*)&sm[k][0];
            float4 p1 = *(const float4*)&sm[k][4];
            o[0] += p0.x * wm;  o[1] += p0.y * wm;
            o[2] += p0.z * wm;  o[3] += p0.w * wm;
            o[4] += p1.x * wm;  o[5] += p1.y * wm;
            o[6] += p1.z * wm;  o[7] += p1.w * wm;
        }
#pragma unroll
        for (int t = 0; t < WPB; t++) out[(w0 + t) * OUT + h] = o[t];
    }
}

// ---------------- launch ----------------
extern "C" void kernel_launch(void* const* d_in, const int* in_sizes, int n_in,
                              void* d_out, int out_size)
{
    const float* cell_x  = (const float*)d_in[0];
    const float* well_x  = (const float*)d_in[1];
    const int*   ei_cell = (const int*)  d_in[2];
    const int*   ews     = (const int*)  d_in[3];
    const int*   ewd     = (const int*)  d_in[4];
    const float* W_cell  = (const float*)d_in[5];
    const float* b_cell  = (const float*)d_in[6];
    const float* W_well  = (const float*)d_in[7];
    const float* b_well  = (const float*)d_in[8];
    const float* Wl_cc   = (const float*)d_in[9];
    const float* bl_cc   = (const float*)d_in[10];
    const float* Wr_cc   = (const float*)d_in[11];
    const float* Wl_cw   = (const float*)d_in[12];
    const float* bl_cw   = (const float*)d_in[13];
    const float* Wr_cw   = (const float*)d_in[14];
    const float* W_m1    = (const float*)d_in[15];
    const float* b_m1    = (const float*)d_in[16];
    const float* W_m2    = (const float*)d_in[17];
    const float* b_m2    = (const float*)d_in[18];
    float* out = (float*)d_out;

    // order chosen so k_cc is the 4th launch (ncu profiles launch #4)
    k_init<<<(N_CELL * CF + 255) / 256, 256>>>();
    k_mark<<<(E_CW + 255) / 256, 256>>>(ews);
    k_f1<<<43, 256>>>(W_cell, b_cell, Wl_cc, Wr_cc, bl_cc, W_well, b_well, Wr_cw, bl_cw);
    k_cc<<<(E_CC + 255) / 256, 256>>>(ei_cell, cell_x);
    k_f2<<<34, 256>>>(Wl_cw);
    k_f3<<<43, 256>>>(W_m1, b_m1);
    k_cw<<<(E_CW + 255) / 256, 256>>>(ews, ewd, cell_x);
    k_well<<<N_WELL / WPB, H>>>(well_x, W_m2, b_m2, out);
}

// round 5
// speedup vs baseline: 1.1626x; 1.1626x over previous
#include <cuda_runtime.h>
#include <cstdint>

#define N_CELL 200000
#define N_WELL 2000
#define E_CC   1200000
#define E_CW   200000
#define CF     16
#define WF     8
#define H      128
#define OUT    75
#define WPB    8
#define R      16

// ---------------- device scratch ----------------
__device__ __align__(16) float g_aggx[(size_t)N_CELL * CF];
__device__ int      g_cnt[N_CELL];
__device__ unsigned g_bm[(N_CELL + 31) / 32];
__device__ __align__(16) float g_Ur[(size_t)R * N_WELL * CF];
__device__ __align__(16) float g_Vr[(size_t)R * N_WELL * CF];
__device__ __align__(16) float g_meta[(size_t)R * N_WELL * 4];

// fused-weight pipeline
// F rows: [0,16) M1 (Un), [16,32) M2 (Vn), 32 v1 (beta_n), 33 v2 (mask),
//         [34,42) M3 (wx), 42 v3 (const)
__device__ float g_T1[43 * H];
__device__ float g_T2[34 * H];
__device__ float g_F[43 * H];

__device__ __forceinline__ void red4(float* p, float a, float b, float c, float d) {
    asm volatile("red.global.add.v4.f32 [%0], {%1,%2,%3,%4};"
                 :: "l"(p), "f"(a), "f"(b), "f"(c), "f"(d) : "memory");
}

// ---------------- zero kernels ----------------
__global__ void k_zero_cell() {           // aggx (float4), cnt, bm
    int i = blockIdx.x * blockDim.x + threadIdx.x;
    if (i < N_CELL * CF / 4) ((float4*)g_aggx)[i] = make_float4(0.f, 0.f, 0.f, 0.f);
    if (i < N_CELL) g_cnt[i] = 0;
    if (i < (N_CELL + 31) / 32) g_bm[i] = 0u;
}
__global__ void k_zero_well() {           // Ur, Vr (float4), meta (float4)
    int i = blockIdx.x * blockDim.x + threadIdx.x;
    if (i < R * N_WELL * CF / 4) {
        ((float4*)g_Ur)[i] = make_float4(0.f, 0.f, 0.f, 0.f);
        ((float4*)g_Vr)[i] = make_float4(0.f, 0.f, 0.f, 0.f);
    }
    if (i < R * N_WELL) ((float4*)g_meta)[i] = make_float4(0.f, 0.f, 0.f, 0.f);
}

// ---------------- K2: mark active cells ----------------
__global__ void k_mark(const int* __restrict__ ews) {
    int e = blockIdx.x * blockDim.x + threadIdx.x;
    if (e >= E_CW) return;
    int s = __ldg(&ews[e]);
    atomicOr(&g_bm[s >> 5], 1u << (s & 31));
}

// ---------------- fuse-stage body: one output row per block, 256 thr ----
__device__ __forceinline__ void stage_row(const float* __restrict__ L,
                                          const float* __restrict__ M,
                                          float* __restrict__ dst,
                                          const float* __restrict__ addv,
                                          float* sL, float* sP)
{
    int tid  = threadIdx.x;
    int h    = tid & (H - 1);
    int half = tid >> 7;
    if (half == 0) sL[h] = __ldg(&L[h]);
    __syncthreads();
    float acc = 0.f;
    int k0 = half * 64;
#pragma unroll 16
    for (int k = 0; k < 64; k++)
        acc += sL[k0 + k] * __ldg(&M[(k0 + k) * H + h]);
    sP[tid] = acc;
    __syncthreads();
    if (half == 0) {
        float v = sP[h] + sP[h + 128];
        if (addv) v += __ldg(&addv[h]);
        dst[h] = v;
    }
}

__global__ void __launch_bounds__(256) k_f1(
    const float* __restrict__ W_cell, const float* __restrict__ b_cell,
    const float* __restrict__ Wl_cc, const float* __restrict__ Wr_cc,
    const float* __restrict__ bl_cc,
    const float* __restrict__ W_well, const float* __restrict__ b_well,
    const float* __restrict__ Wr_cw, const float* __restrict__ bl_cw)
{
    __shared__ float sL[H];
    __shared__ float sP[256];
    int r = blockIdx.x;
    const float* L; const float* M; const float* A = nullptr;
    if (r < 16)      { L = W_cell + r * H;        M = Wl_cc; }
    else if (r < 32) { L = W_cell + (r - 16) * H; M = Wr_cc; }
    else if (r == 32){ L = b_cell;                M = Wl_cc; }
    else if (r == 33){ L = b_cell;                M = Wr_cc; A = bl_cc; }
    else if (r < 42) { L = W_well + (r - 34) * H; M = Wr_cw; }
    else             { L = b_well;                M = Wr_cw; A = bl_cw; }
    stage_row(L, M, g_T1 + r * H, A, sL, sP);
}

__global__ void __launch_bounds__(256) k_f2(const float* __restrict__ Wl_cw)
{
    __shared__ float sL[H];
    __shared__ float sP[256];
    int r = blockIdx.x;
    stage_row(g_T1 + r * H, Wl_cw, g_T2 + r * H, nullptr, sL, sP);
}

__global__ void __launch_bounds__(256) k_f3(const float* __restrict__ Wm1,
                                            const float* __restrict__ bm1)
{
    __shared__ float sL[H];
    __shared__ float sP[256];
    int r = blockIdx.x;
    const float* L = (r < 34) ? (g_T2 + r * H) : (g_T1 + r * H);
    const float* A = (r == 42) ? bm1 : nullptr;
    stage_row(L, Wm1, g_F + r * H, A, sL, sP);
}

// ---------------- K3: scan cell-cell edges (2 edges/thread) ----------------
__global__ void k_cc(const int* __restrict__ ei, const float* __restrict__ x) {
    int t = blockIdx.x * blockDim.x + threadIdx.x;
    if (t >= E_CC / 2) return;
#pragma unroll
    for (int half = 0; half < 2; half++) {
        int e = t + half * (E_CC / 2);
        int d = __ldg(&ei[E_CC + e]);
        if ((g_bm[d >> 5] >> (d & 31)) & 1u) {
            int s = __ldg(&ei[e]);
            const float4* xp = (const float4*)(x + (size_t)s * CF);
            float* ap = g_aggx + (size_t)d * CF;
            float4 v0 = __ldg(xp + 0), v1 = __ldg(xp + 1), v2 = __ldg(xp + 2), v3 = __ldg(xp + 3);
            red4(ap + 0,  v0.x, v0.y, v0.z, v0.w);
            red4(ap + 4,  v1.x, v1.y, v1.z, v1.w);
            red4(ap + 8,  v2.x, v2.y, v2.z, v2.w);
            red4(ap + 12, v3.x, v3.y, v3.z, v3.w);
            atomicAdd(&g_cnt[d], 1);
        }
    }
}

// ---------------- K4: scan cell-well edges ----------------
__global__ void k_cw(const int* __restrict__ ews, const int* __restrict__ ewd,
                     const float* __restrict__ x) {
    int e = blockIdx.x * blockDim.x + threadIdx.x;
    if (e >= E_CW) return;
    int rep = blockIdx.x & (R - 1);
    int s = __ldg(&ews[e]);
    int w = __ldg(&ewd[e]);
    int c = g_cnt[s];
    float inv = (c > 0) ? (1.f / (float)c) : 0.f;
    const float4* ap = (const float4*)(g_aggx + (size_t)s * CF);
    const float4* xp = (const float4*)(x + (size_t)s * CF);
    float* U = g_Ur + ((size_t)rep * N_WELL + w) * CF;
    float* V = g_Vr + ((size_t)rep * N_WELL + w) * CF;
    float4 a0 = ap[0], a1 = ap[1], a2 = ap[2], a3 = ap[3];
    red4(U + 0,  a0.x * inv, a0.y * inv, a0.z * inv, a0.w * inv);
    red4(U + 4,  a1.x * inv, a1.y * inv, a1.z * inv, a1.w * inv);
    red4(U + 8,  a2.x * inv, a2.y * inv, a2.z * inv, a2.w * inv);
    red4(U + 12, a3.x * inv, a3.y * inv, a3.z * inv, a3.w * inv);
    float4 b0 = __ldg(xp + 0), b1 = __ldg(xp + 1), b2 = __ldg(xp + 2), b3 = __ldg(xp + 3);
    red4(V + 0,  b0.x, b0.y, b0.z, b0.w);
    red4(V + 4,  b1.x, b1.y, b1.z, b1.w);
    red4(V + 8,  b2.x, b2.y, b2.z, b2.w);
    red4(V + 12, b3.x, b3.y, b3.z, b3.w);
    red4(g_meta + ((size_t)rep * N_WELL + w) * 4, (c > 0) ? 1.f : 0.f, 1.f, 0.f, 0.f);
}

// ---------------- K6: per-well head ----------------
__global__ void __launch_bounds__(H) k_well(
    const float* __restrict__ well_x,
    const float* __restrict__ Wm2, const float* __restrict__ bm2,
    float* __restrict__ out)
{
    __shared__ __align__(16) float sm[H][WPB];
    __shared__ float sUn[WPB][CF], sVn[WPB][CF], sWX[WPB][WF];
    __shared__ float sb1[WPB], sb2[WPB], sinv[WPB];

    int h  = threadIdx.x;
    int w0 = blockIdx.x * WPB;

    if (h < WPB) {
        float beta = 0.f, cw = 0.f;
#pragma unroll
        for (int r = 0; r < R; r++) {
            const float* mp = g_meta + ((size_t)r * N_WELL + (w0 + h)) * 4;
            beta += mp[0];
            cw   += mp[1];
        }
        float inv = 1.f / fmaxf(cw, 1.f);
        sinv[h] = inv;
        sb1[h]  = beta * inv;
        sb2[h]  = (cw > 0.5f) ? 1.f : 0.f;
    }
    __syncthreads();
    {
        int t = h >> 4, j = h & 15;
        float su = 0.f, svv = 0.f;
#pragma unroll
        for (int r = 0; r < R; r++) {
            size_t off = ((size_t)r * N_WELL + (w0 + t)) * CF + j;
            su  += g_Ur[off];
            svv += g_Vr[off];
        }
        sUn[t][j] = su * sinv[t];
        sVn[t][j] = svv * sinv[t];
    }
    if (h < WPB * WF) {
        int t = h >> 3, j = h & 7;
        sWX[t][j] = __ldg(&well_x[(w0 + t) * WF + j]);
    }
    __syncthreads();

    float acc[WPB];
    {
        float f1 = g_F[32 * H + h], f2 = g_F[33 * H + h], f3 = g_F[42 * H + h];
#pragma unroll
        for (int t = 0; t < WPB; t++) acc[t] = f3 + sb1[t] * f1 + sb2[t] * f2;
    }
#pragma unroll
    for (int j = 0; j < CF; j++) {
        float m1 = g_F[j * H + h];
        float m2 = g_F[(16 + j) * H + h];
#pragma unroll
        for (int t = 0; t < WPB; t++) acc[t] += sUn[t][j] * m1 + sVn[t][j] * m2;
    }
#pragma unroll
    for (int j = 0; j < WF; j++) {
        float m3 = g_F[(34 + j) * H + h];
#pragma unroll
        for (int t = 0; t < WPB; t++) acc[t] += sWX[t][j] * m3;
    }
#pragma unroll
    for (int t = 0; t < WPB; t++) sm[h][t] = fmaxf(acc[t], 0.f);
    __syncthreads();

    if (h < OUT) {
        float o[WPB];
        float bv = __ldg(&bm2[h]);
#pragma unroll
        for (int t = 0; t < WPB; t++) o[t] = bv;
#pragma unroll 4
        for (int k = 0; k < H; k++) {
            float wm = __ldg(&Wm2[k * OUT + h]);
            float4 p0 = *(const float4*)&sm[k][0];
            float4 p1 = *(const float4*)&sm[k][4];
            o[0] += p0.x * wm;  o[1] += p0.y * wm;
            o[2] += p0.z * wm;  o[3] += p0.w * wm;
            o[4] += p1.x * wm;  o[5] += p1.y * wm;
            o[6] += p1.z * wm;  o[7] += p1.w * wm;
        }
#pragma unroll
        for (int t = 0; t < WPB; t++) out[(w0 + t) * OUT + h] = o[t];
    }
}

// ---------------- launch (fork-join over 2 streams, capture-safe) ---------
static cudaStream_t s1;
static cudaEvent_t evRoot, evW;
static bool g_host_init = false;

extern "C" void kernel_launch(void* const* d_in, const int* in_sizes, int n_in,
                              void* d_out, int out_size)
{
    if (!g_host_init) {
        cudaStreamCreateWithFlags(&s1, cudaStreamNonBlocking);
        cudaEventCreateWithFlags(&evRoot, cudaEventDisableTiming);
        cudaEventCreateWithFlags(&evW, cudaEventDisableTiming);
        g_host_init = true;
    }

    const float* cell_x  = (const float*)d_in[0];
    const float* well_x  = (const float*)d_in[1];
    const int*   ei_cell = (const int*)  d_in[2];
    const int*   ews     = (const int*)  d_in[3];
    const int*   ewd     = (const int*)  d_in[4];
    const float* W_cell  = (const float*)d_in[5];
    const float* b_cell  = (const float*)d_in[6];
    const float* W_well  = (const float*)d_in[7];
    const float* b_well  = (const float*)d_in[8];
    const float* Wl_cc   = (const float*)d_in[9];
    const float* bl_cc   = (const float*)d_in[10];
    const float* Wr_cc   = (const float*)d_in[11];
    const float* Wl_cw   = (const float*)d_in[12];
    const float* bl_cw   = (const float*)d_in[13];
    const float* Wr_cw   = (const float*)d_in[14];
    const float* W_m1    = (const float*)d_in[15];
    const float* b_m1    = (const float*)d_in[16];
    const float* W_m2    = (const float*)d_in[17];
    const float* b_m2    = (const float*)d_in[18];
    float* out = (float*)d_out;

    // fork
    cudaEventRecord(evRoot, 0);
    cudaStreamWaitEvent(s1, evRoot, 0);

    // side stream: fuse chain + well-accumulator zeroing (independent of edges)
    k_f1<<<43, 256, 0, s1>>>(W_cell, b_cell, Wl_cc, Wr_cc, bl_cc, W_well, b_well, Wr_cw, bl_cw);
    k_f2<<<34, 256, 0, s1>>>(Wl_cw);
    k_f3<<<43, 256, 0, s1>>>(W_m1, b_m1);
    k_zero_well<<<(R * N_WELL * CF / 4 + 255) / 256, 256, 0, s1>>>();
    cudaEventRecord(evW, s1);

    // main stream: critical path
    k_zero_cell<<<(N_CELL * CF / 4 + 255) / 256, 256>>>();
    k_mark<<<(E_CW + 255) / 256, 256>>>(ews);
    k_cc<<<(E_CC / 2 + 255) / 256, 256>>>(ei_cell, cell_x);
    cudaStreamWaitEvent(0, evW, 0);   // join side stream
    k_cw<<<(E_CW + 255) / 256, 256>>>(ews, ewd, cell_x);
    k_well<<<N_WELL / WPB, H>>>(well_x, W_m2, b_m2, out);
}